// round 4
// baseline (speedup 1.0000x reference)
#include <cuda_runtime.h>
#include <stdint.h>

// Problem constants (fixed by the reference problem definition)
#define FEAT_DIM 128
#define BATCH    4
#define NY       512
#define NX       512
#define NYNX     (NY * NX)
#define NPIX     (BATCH * NYNX)      // 1,048,576

#define XT   64        // x-tile per block
#define NTH  512       // 16 warps -> 4 blocks/SM = 64 warps = 100% occ, smem 128KB

// 4 MB scratch: winner map. INVARIANT: all-zero on entry to kernel_launch.
//  - zero at module load (device globals are zero-initialized)
//  - k_argmax writes (voxel_index + 1) via atomicMax (last-write-wins == max idx)
//  - k_gather restores every nonzero entry it consumed back to 0
// => no init kernel, identical work every call (graph-replay safe).
__device__ int g_map[NPIX];

// ---------------------------------------------------------------------------
// Kernel 1: winner per pixel.  coors: [N,4] int32 (b, z, y, x)
// ---------------------------------------------------------------------------
__global__ void k_argmax_map(const int* __restrict__ coors, int n) {
    int i = blockIdx.x * blockDim.x + threadIdx.x;
    if (i >= n) return;
    int4 c = reinterpret_cast<const int4*>(coors)[i];  // b, z, y, x
    int flat = c.x * NYNX + c.z * NX + c.w;
    atomicMax(&g_map[flat], i + 1);
}

// ---------------------------------------------------------------------------
// Kernel 2: gather + transpose, fully 128-bit vectorized via quad XOR swizzle.
// Tile: 64 pixels x 128 channels, physical float index
//   P(x, c) = x*128 + ((c>>2 ^ (x&31)) << 2) + (c&3)
// Fill : warp=pixel, lane=quad  -> LDG.128 + STS.128, conflict-free.
// Drain: lane=x, fixed quad     -> LDS.128 conflict-free + 4x coalesced STG.32.
// Writes the FULL output (zeros for empty pixels).
// ---------------------------------------------------------------------------
__global__ __launch_bounds__(NTH)
void k_gather(const float* __restrict__ feat, float* __restrict__ out) {
    __shared__ float tile[XT * FEAT_DIM];   // 32 KB, swizzled

    int blk = blockIdx.x;              // 0 .. BATCH*NY*(NX/XT)-1
    int xt  = blk & (NX / XT - 1);     // 0..7
    int y   = (blk >> 3) & (NY - 1);   // 0..511
    int b   = blk >> 12;               // 0..3
    int x0  = xt * XT;

    int t = threadIdx.x, warp = t >> 5, lane = t & 31;
    int mapbase = b * NYNX + y * NX + x0;

    // ---- Fill: 16 warps x 4 pixels each ----
    #pragma unroll
    for (int m = 0; m < XT / 16; m++) {
        int xl  = m * 16 + warp;
        int idx = mapbase + xl;
        int v   = g_map[idx];                       // uniform broadcast load
        float4 val;
        if (v > 0) {
            val = reinterpret_cast<const float4*>(
                      feat + (size_t)(v - 1) * FEAT_DIM)[lane];   // LDG.128
            if (lane == 0) g_map[idx] = 0;          // restore invariant
        } else {
            val = make_float4(0.f, 0.f, 0.f, 0.f);
        }
        int sw = (lane ^ (xl & 31)) << 2;           // quad swizzle
        *reinterpret_cast<float4*>(&tile[xl * FEAT_DIM + sw]) = val;  // STS.128
    }
    __syncthreads();

    // ---- Drain: 64 items (quad q 0..31, x-half) / 16 warps = 4 each ----
    size_t pixbase = (size_t)b * FEAT_DIM * NYNX + (size_t)y * NX + x0;
    #pragma unroll
    for (int m = 0; m < 4; m++) {
        int item = m * 16 + warp;                   // 0..63
        int q    = item >> 1;                       // channel quad 0..31
        int x    = ((item & 1) << 5) + lane;        // 0..63
        float4 val = *reinterpret_cast<const float4*>(
            &tile[x * FEAT_DIM + ((q ^ (x & 31)) << 2)]);         // LDS.128
        size_t o = pixbase + (size_t)(4 * q) * NYNX + x;
        out[o]            = val.x;                  // 4 x 128B coalesced STG
        out[o +     NYNX] = val.y;
        out[o + 2 * NYNX] = val.z;
        out[o + 3 * NYNX] = val.w;
    }
}

// ---------------------------------------------------------------------------
extern "C" void kernel_launch(void* const* d_in, const int* in_sizes, int n_in,
                              void* d_out, int out_size) {
    const float* feat  = (const float*)d_in[0];
    const int*   coors = (const int*)d_in[1];
    float*       out   = (float*)d_out;

    int n = in_sizes[0] / FEAT_DIM;   // number of voxels

    // 1) winner per pixel (map is all-zero by invariant)
    k_argmax_map<<<(n + 255) / 256, 256>>>(coors, n);
    // 2) gather + transpose full output (and restore map to zero)
    k_gather<<<BATCH * NY * (NX / XT), NTH>>>(feat, out);
}